// round 2
// baseline (speedup 1.0000x reference)
#include <cuda_runtime.h>
#include <cuda_bf16.h>

// BuzzLoss: B=8192 rows, T=1024 cols.
// One WARP per row; each thread owns 32 contiguous elements (8x float4 per
// input). Per-thread local exclusive-prefix accumulation factorizes:
//   s1 = sum_t E_t * s1_local_t,  E_t = exclusive warp product-scan of P_t.
// No mid-kernel barriers; 16 independent LDG.128 per thread for high MLP.

#define FULL_MASK 0xFFFFFFFFu

__global__ void buzz_zero_kernel(float* out) {
    out[0] = 0.0f;
}

__global__ __launch_bounds__(256)
void buzz_loss_kernel(const float* __restrict__ conf,
                      const float* __restrict__ acc,
                      float* __restrict__ out,
                      float negInvB) {
    const int tid  = threadIdx.x;
    const int lane = tid & 31;
    const int wid  = tid >> 5;
    const int row  = (blockIdx.x << 3) + wid;   // 8 rows per CTA

    __shared__ float s_score[8];

    const float4* c4 = reinterpret_cast<const float4*>(conf + (size_t)row * 1024) + lane * 8;
    const float4* a4 = reinterpret_cast<const float4*>(acc  + (size_t)row * 1024) + lane * 8;

    float pref = 1.0f;          // running local exclusive prefix (starts at 1)
    float s1 = 0.0f, s2 = 0.0f;
    float lastA = 0.0f;

    #pragma unroll
    for (int j = 0; j < 8; j++) {
        const float4 c = c4[j];
        const float4 a = a4[j];
        float b;
        b = c.x * pref; s1 = fmaf(b, a.x, s1); s2 += b; pref *= (1.0f - c.x);
        b = c.y * pref; s1 = fmaf(b, a.y, s1); s2 += b; pref *= (1.0f - c.y);
        b = c.z * pref; s1 = fmaf(b, a.z, s1); s2 += b; pref *= (1.0f - c.z);
        b = c.w * pref; s1 = fmaf(b, a.w, s1); s2 += b; pref *= (1.0f - c.w);
        if (j == 7) lastA = a.w;   // lane 31 j==7 -> acc[row, 1023]
    }
    // pref == P_t: product of this thread's 32 (1-c) factors.

    // Warp inclusive product-scan of P_t, then shift to exclusive.
    float inc = pref;
    #pragma unroll
    for (int d = 1; d < 32; d <<= 1) {
        float v = __shfl_up_sync(FULL_MASK, inc, d);
        if (lane >= d) inc *= v;
    }
    float E = __shfl_up_sync(FULL_MASK, inc, 1);
    if (lane == 0) E = 1.0f;

    s1 *= E;
    s2 *= E;

    // Warp reduce s1, s2.
    #pragma unroll
    for (int d = 16; d >= 1; d >>= 1) {
        s1 += __shfl_down_sync(FULL_MASK, s1, d);
        s2 += __shfl_down_sync(FULL_MASK, s2, d);
    }

    const float accLast = __shfl_sync(FULL_MASK, lastA, 31);

    if (lane == 0) {
        s_score[wid] = s1 + (1.0f - s2) * accLast;
    }
    __syncthreads();

    if (wid == 0) {
        float t = (lane < 8) ? s_score[lane] : 0.0f;
        #pragma unroll
        for (int d = 4; d >= 1; d >>= 1) {
            t += __shfl_down_sync(FULL_MASK, t, d);
        }
        if (lane == 0) {
            atomicAdd(out, t * negInvB);
        }
    }
}

extern "C" void kernel_launch(void* const* d_in, const int* in_sizes, int n_in,
                              void* d_out, int out_size) {
    const float* conf = (const float*)d_in[0];
    const float* acc  = (const float*)d_in[1];
    float* out = (float*)d_out;

    const int total = in_sizes[0];
    const int T = 1024;
    const int B = total / T;
    const int rowsPerCta = 8;

    buzz_zero_kernel<<<1, 1>>>(out);
    buzz_loss_kernel<<<B / rowsPerCta, 256>>>(conf, acc, out, -1.0f / (float)B);
}

// round 3
// speedup vs baseline: 1.0155x; 1.0155x over previous
#include <cuda_runtime.h>
#include <cuda_bf16.h>

// BuzzLoss: B=8192 rows, T=1024 cols.
// 4 rows per 256-thread CTA. Each thread owns 4 contiguous floats of each row
// (coalesced float4 per warp), 8 independent LDG.128 front-batched per thread.
// Per-row: local prefix -> warp product-scan -> 8-warp smem combine; the four
// rows' dependent shfl chains interleave for ILP.

#define FULL_MASK 0xFFFFFFFFu
#define ROWS 4

__global__ void buzz_zero_kernel(float* out) {
    out[0] = 0.0f;
}

__global__ __launch_bounds__(256)
void buzz_loss_kernel(const float* __restrict__ conf,
                      const float* __restrict__ acc,
                      float* __restrict__ out,
                      float negInvB) {
    const int tid  = threadIdx.x;
    const int lane = tid & 31;
    const int wid  = tid >> 5;
    const int row0 = blockIdx.x * ROWS;

    __shared__ float s_warp_prod[ROWS][8];
    __shared__ float s_s1[ROWS][8];
    __shared__ float s_s2[ROWS][8];
    __shared__ float s_acc_last[ROWS];

    // Front-batched loads: 8 independent LDG.128
    float4 c[ROWS], a[ROWS];
    #pragma unroll
    for (int r = 0; r < ROWS; r++) {
        const size_t base = (size_t)(row0 + r) * 1024;
        c[r] = reinterpret_cast<const float4*>(conf + base)[tid];
        a[r] = reinterpret_cast<const float4*>(acc  + base)[tid];
    }

    float inc[ROWS], excl[ROWS];

    #pragma unroll
    for (int r = 0; r < ROWS; r++) {
        const float q0 = 1.0f - c[r].x;
        const float q1 = 1.0f - c[r].y;
        const float q2 = 1.0f - c[r].z;
        // local product of all 4 factors
        inc[r] = q0 * q1 * q2 * (1.0f - c[r].w);
        // stash local partials for later (recomputed cheaply below)
        (void)0;
    }

    // Warp inclusive product-scan of per-thread products (4 rows interleaved)
    #pragma unroll
    for (int d = 1; d < 32; d <<= 1) {
        #pragma unroll
        for (int r = 0; r < ROWS; r++) {
            float v = __shfl_up_sync(FULL_MASK, inc[r], d);
            if (lane >= d) inc[r] *= v;
        }
    }
    #pragma unroll
    for (int r = 0; r < ROWS; r++) {
        excl[r] = __shfl_up_sync(FULL_MASK, inc[r], 1);
        if (lane == 0) excl[r] = 1.0f;
        if (lane == 31) s_warp_prod[r][wid] = inc[r];
    }
    if (tid == 255) {
        #pragma unroll
        for (int r = 0; r < ROWS; r++) s_acc_last[r] = a[r].w;
    }
    __syncthreads();

    float s1[ROWS], s2[ROWS];
    #pragma unroll
    for (int r = 0; r < ROWS; r++) {
        // exclusive product of preceding warps (8 warps)
        float wpref = 1.0f;
        #pragma unroll
        for (int w = 0; w < 8; w++) {
            if (w < wid) wpref *= s_warp_prod[r][w];
        }
        float E = wpref * excl[r];

        const float q0 = 1.0f - c[r].x;
        const float q1 = 1.0f - c[r].y;
        const float q2 = 1.0f - c[r].z;

        const float b0 = c[r].x * E;
        const float b1 = c[r].y * (E * q0);
        const float b2 = c[r].z * (E * q0 * q1);
        const float b3 = c[r].w * (E * q0 * q1 * q2);

        s1[r] = fmaf(b0, a[r].x, fmaf(b1, a[r].y, fmaf(b2, a[r].z, b3 * a[r].w)));
        s2[r] = (b0 + b1) + (b2 + b3);
    }

    // Warp reduce (4 rows interleaved)
    #pragma unroll
    for (int d = 16; d >= 1; d >>= 1) {
        #pragma unroll
        for (int r = 0; r < ROWS; r++) {
            s1[r] += __shfl_down_sync(FULL_MASK, s1[r], d);
            s2[r] += __shfl_down_sync(FULL_MASK, s2[r], d);
        }
    }
    if (lane == 0) {
        #pragma unroll
        for (int r = 0; r < ROWS; r++) {
            s_s1[r][wid] = s1[r];
            s_s2[r][wid] = s2[r];
        }
    }
    __syncthreads();

    // Warp w (w < ROWS) reduces row w across its 8 warp-partials.
    if (wid < ROWS) {
        float t1 = (lane < 8) ? s_s1[wid][lane] : 0.0f;
        float t2 = (lane < 8) ? s_s2[wid][lane] : 0.0f;
        #pragma unroll
        for (int d = 4; d >= 1; d >>= 1) {
            t1 += __shfl_down_sync(FULL_MASK, t1, d);
            t2 += __shfl_down_sync(FULL_MASK, t2, d);
        }
        if (lane == 0) {
            float score = t1 + (1.0f - t2) * s_acc_last[wid];
            atomicAdd(out, score * negInvB);
        }
    }
}

extern "C" void kernel_launch(void* const* d_in, const int* in_sizes, int n_in,
                              void* d_out, int out_size) {
    const float* conf = (const float*)d_in[0];
    const float* acc  = (const float*)d_in[1];
    float* out = (float*)d_out;

    const int total = in_sizes[0];
    const int T = 1024;
    const int B = total / T;

    buzz_zero_kernel<<<1, 1>>>(out);
    buzz_loss_kernel<<<B / ROWS, 256>>>(conf, acc, out, -1.0f / (float)B);
}